// round 7
// baseline (speedup 1.0000x reference)
#include <cuda_runtime.h>
#include <cstdint>

// Problem constants (fixed by reference setup_inputs)
#define BATCH 2
#define HH 48
#define WW 48
#define CC 512
#define NH 8
#define HD 64
#define KK 7
#define NPIX (BATCH*HH*WW)          // 4608
#define QKV_M (3*CC)                 // 1536

// Scratch (static device globals; 16B-aligned for vector access)
__device__ __align__(16) float g_qkv[(size_t)NPIX * QKV_M];   // 28.3 MB
__device__ __align__(16) float g_att[(size_t)NPIX * CC];      // 9.4 MB (tf32-rounded)
__device__ __align__(16) float g_x  [(size_t)NPIX * CC];      // 9.4 MB (tf32-rounded x)
__device__ __align__(16) float g_w1 [(size_t)QKV_M * CC];     // 3.0 MB (tf32 qkv_w)
__device__ __align__(16) float g_w2 [(size_t)CC * CC];        // 1.0 MB (tf32 proj_w)

// ---------------------------------------------------------------------------
// helpers
// ---------------------------------------------------------------------------
__device__ __forceinline__ uint32_t smem_u32(const void* p) {
    uint32_t a;
    asm("{ .reg .u64 t; cvta.to.shared.u64 t, %1; cvt.u32.u64 %0, t; }" : "=r"(a) : "l"(p));
    return a;
}
__device__ __forceinline__ uint32_t f2tf32(float x) {
    uint32_t r; asm("cvt.rna.tf32.f32 %0, %1;" : "=r"(r) : "f"(x)); return r;
}
__device__ __forceinline__ float f2tf32f(float x) {
    return __uint_as_float(f2tf32(x));
}
#define CP16(dst, src)  asm volatile("cp.async.cg.shared.global [%0], [%1], 16;" :: "r"(dst), "l"(src) : "memory")
#define CP_COMMIT()     asm volatile("cp.async.commit_group;" ::: "memory")
#define CP_WAIT(n)      asm volatile("cp.async.wait_group %0;" :: "n"(n) : "memory")

#define MMA_TF32(c, a, b) \
    asm volatile("mma.sync.aligned.m16n8k8.row.col.f32.tf32.tf32.f32 " \
        "{%0,%1,%2,%3}, {%4,%5,%6,%7}, {%8,%9}, {%0,%1,%2,%3};" \
        : "+f"((c)[0]), "+f"((c)[1]), "+f"((c)[2]), "+f"((c)[3]) \
        : "r"((a)[0]), "r"((a)[1]), "r"((a)[2]), "r"((a)[3]), "r"((b)[0]), "r"((b)[1]))

// ---------------------------------------------------------------------------
// elementwise tf32 rounding (pre-conversion of GEMM inputs)
// ---------------------------------------------------------------------------
__global__ __launch_bounds__(256) void cvt_tf32_kernel(
    const float4* __restrict__ in, float4* __restrict__ out, int n4)
{
    int i = blockIdx.x * 256 + threadIdx.x;
    if (i < n4) {
        float4 f = in[i];
        float4 o = { f2tf32f(f.x), f2tf32f(f.y), f2tf32f(f.z), f2tf32f(f.w) };
        out[i] = o;
    }
}

// ---------------------------------------------------------------------------
// tf32 warp-MMA GEMM: C[M][Ncols] = A[M,K] * B[Ncols,K]^T + bias[Ncols]
// CTA tile 128 x BNR; 8 warps (2x4), warp tile 64 x (BNR/4).
// BNR chosen per-launch for wave balance (96 for qkv, 64 for proj).
// A, B must already be tf32-rounded. Stride 36 -> conflict-free fragments.
// ---------------------------------------------------------------------------
template<int BNR>
__global__ __launch_bounds__(256, 2) void gemm_mma(
    const float* __restrict__ A, const float* __restrict__ B,
    const float* __restrict__ bias, float* __restrict__ C,
    int K, int Ncols)
{
    constexpr int NT = BNR / 32;          // n8-tiles per warp
    constexpr int ABUF = 128 * 36;        // floats per A buffer
    constexpr int BBUF = BNR * 36;        // floats per B buffer

    extern __shared__ float sm[];
    const uint32_t sb = smem_u32(sm);

    const int t = threadIdx.x;
    const int lane = t & 31, wid = t >> 5;
    const int g = lane >> 2, tg = lane & 3;
    const int wm = wid >> 2, wn = wid & 3;
    const int m0 = blockIdx.y * 128, n0 = blockIdx.x * BNR;

    const int ldr = t >> 3;
    const int ldc = t & 7;

    float acc[4][NT][4];
    #pragma unroll
    for (int i = 0; i < 4; i++)
        #pragma unroll
        for (int j = 0; j < NT; j++)
            #pragma unroll
            for (int r = 0; r < 4; r++) acc[i][j][r] = 0.f;

    const int nch = K >> 5;

    auto issue = [&](int ch, int buf) {
        const float* Ac = A + (size_t)m0 * K + ch * 32;
        const float* Bc = B + (size_t)n0 * K + ch * 32;
        uint32_t dA = sb + buf * (ABUF * 4);
        uint32_t dB = sb + 2 * (ABUF * 4) + buf * (BBUF * 4);
        #pragma unroll
        for (int i = 0; i < 4; i++) {
            int row = ldr + i * 32;
            CP16(dA + row * 144 + ldc * 16, Ac + (size_t)row * K + ldc * 4);
        }
        #pragma unroll
        for (int i = 0; i < BNR / 32; i++) {
            int row = ldr + i * 32;
            CP16(dB + row * 144 + ldc * 16, Bc + (size_t)row * K + ldc * 4);
        }
        CP_COMMIT();
    };

    issue(0, 0);

    for (int ch = 0; ch < nch; ch++) {
        const int buf = ch & 1;
        if (ch + 1 < nch) { issue(ch + 1, buf ^ 1); CP_WAIT(1); }
        else              { CP_WAIT(0); }
        __syncthreads();

        const float* Ab = sm + buf * ABUF;
        const float* Bb = sm + 2 * ABUF + buf * BBUF;

        #pragma unroll
        for (int kk = 0; kk < 4; kk++) {
            uint32_t af[4][4], bf[NT][2];
            #pragma unroll
            for (int mt = 0; mt < 4; mt++) {
                const float* p = Ab + (wm * 64 + mt * 16 + g) * 36 + kk * 8 + tg;
                af[mt][0] = __float_as_uint(p[0]);
                af[mt][1] = __float_as_uint(p[8 * 36]);
                af[mt][2] = __float_as_uint(p[4]);
                af[mt][3] = __float_as_uint(p[8 * 36 + 4]);
            }
            #pragma unroll
            for (int nt = 0; nt < NT; nt++) {
                const float* p = Bb + (wn * (BNR / 4) + nt * 8 + g) * 36 + kk * 8 + tg;
                bf[nt][0] = __float_as_uint(p[0]);
                bf[nt][1] = __float_as_uint(p[4]);
            }
            #pragma unroll
            for (int mt = 0; mt < 4; mt++)
                #pragma unroll
                for (int nt = 0; nt < NT; nt++)
                    MMA_TF32(acc[mt][nt], af[mt], bf[nt]);
        }
        __syncthreads();
    }

    float bb[NT][2];
    #pragma unroll
    for (int nt = 0; nt < NT; nt++) {
        int c = n0 + wn * (BNR / 4) + nt * 8 + 2 * tg;
        bb[nt][0] = __ldg(bias + c);
        bb[nt][1] = __ldg(bias + c + 1);
    }
    #pragma unroll
    for (int mt = 0; mt < 4; mt++) {
        int r = m0 + wm * 64 + mt * 16 + g;
        #pragma unroll
        for (int nt = 0; nt < NT; nt++) {
            int c = n0 + wn * (BNR / 4) + nt * 8 + 2 * tg;
            float2 v0 = { acc[mt][nt][0] + bb[nt][0], acc[mt][nt][1] + bb[nt][1] };
            float2 v1 = { acc[mt][nt][2] + bb[nt][0], acc[mt][nt][3] + bb[nt][1] };
            *(float2*)(C + (size_t)r * Ncols + c) = v0;
            *(float2*)(C + (size_t)(r + 8) * Ncols + c) = v1;
        }
    }
}

#define SM_GEMM_96 ((2*128*36 + 2*96*36) * 4)    // 64512 B
#define SM_GEMM_64 ((2*128*36 + 2*64*36) * 4)    // 55296 B

// ---------------------------------------------------------------------------
// Tensor-core neighborhood attention.
// Block = (head, 8x8 pixel tile). 256 threads = 8 warps.
//   S[64,208] = Q[64,64] * Kw[208,64]^T, masked softmax, O = W * V.
// V stays K-major ([wpix][68]) — WV mma reads B fragments directly from it
// (2-way LDS conflicts, no transpose). Ws overlays the dead Q/K region.
// Coalesced staging for Q, K, V. smem 131KB.
// ---------------------------------------------------------------------------
#define WIN 14
#define NWIN 196
#define NPAD 208
#define QSTR 68
#define WSTR 212

#define OFF_Q  0
#define OFF_K  (OFF_Q + 64*QSTR)            // 4352
#define OFF_V  (OFF_K + NPAD*QSTR)          // 18496
#define OFF_WS 0                            // overlays Q+K (13568 <= 18496)
#define OFF_I  (OFF_V + NPAD*QSTR)          // 32640
#define SM_NATT ((OFF_I + 64) * 4)          // 130816 B

__global__ __launch_bounds__(256) void natt_mma(
    const float* __restrict__ qkv, float* __restrict__ out)
{
    extern __shared__ float sm[];
    float* Qs = sm + OFF_Q;
    float* Ks = sm + OFF_K;
    float* Vs = sm + OFF_V;
    float* Ws = sm + OFF_WS;
    float* invs = sm + OFF_I;

    const int tile = blockIdx.x;
    const int h = blockIdx.y;
    const int b = blockIdx.z;
    const int ti0 = (tile / 6) * 8;
    const int tj0 = (tile % 6) * 8;
    const int wr0 = min(max(ti0 - 3, 0), HH - WIN);
    const int wc0 = min(max(tj0 - 3, 0), WW - WIN);

    const int t = threadIdx.x;
    const int lane = t & 31, wid = t >> 5;
    const int g = lane >> 2, tg = lane & 3;
    const float* base = qkv + (size_t)b * HH * WW * QKV_M;

    // ---- stage Q (scaled + tf32), coalesced
    #pragma unroll
    for (int v = t; v < 64 * 16; v += 256) {
        int pix = v >> 4, dc = v & 15;
        int gi = ti0 + (pix >> 3), gj = tj0 + (pix & 7);
        float4 f = *(const float4*)(base + ((size_t)gi * WW + gj) * QKV_M + h * HD + dc * 4);
        uint4 u = { f2tf32(f.x * 0.125f), f2tf32(f.y * 0.125f),
                    f2tf32(f.z * 0.125f), f2tf32(f.w * 0.125f) };
        *(uint4*)(Qs + pix * QSTR + dc * 4) = u;
    }
    // ---- stage K and V (both [wpix][68], tf32), coalesced
    for (int v = t; v < NWIN * 16; v += 256) {
        int wpix = v >> 4, dc = v & 15;
        int wr = wr0 + wpix / WIN, wc = wc0 + wpix % WIN;
        const float* p = base + ((size_t)wr * WW + wc) * QKV_M + CC + h * HD + dc * 4;
        float4 kf = *(const float4*)p;
        float4 vf = *(const float4*)(p + CC);
        uint4 ku = { f2tf32(kf.x), f2tf32(kf.y), f2tf32(kf.z), f2tf32(kf.w) };
        uint4 vu = { f2tf32(vf.x), f2tf32(vf.y), f2tf32(vf.z), f2tf32(vf.w) };
        *(uint4*)(Ks + wpix * QSTR + dc * 4) = ku;
        *(uint4*)(Vs + wpix * QSTR + dc * 4) = vu;
    }
    // ---- zero V pad rows 196..207 (pad weights are 0; avoid 0*NaN)
    #pragma unroll
    for (int v = t; v < 12 * 64; v += 256) {
        Vs[(NWIN + (v >> 6)) * QSTR + (v & 63)] = 0.f;
    }
    __syncthreads();

    // ---- QK^T: warp (wm 0..3, wn 0..1); 16 rows x 104 cols per warp
    float sacc[13][4];
    {
        const int wm = wid >> 1, wn = wid & 1;
        #pragma unroll
        for (int nt = 0; nt < 13; nt++)
            #pragma unroll
            for (int r = 0; r < 4; r++) sacc[nt][r] = 0.f;

        const float* q0 = Qs + (wm * 16 + g) * QSTR + tg;
        const float* q1 = q0 + 8 * QSTR;
        const float* kb = Ks + (wn * 104 + g) * QSTR + tg;

        #pragma unroll
        for (int k = 0; k < 8; k++) {
            uint32_t af[4];
            af[0] = __float_as_uint(q0[k * 8]);
            af[1] = __float_as_uint(q1[k * 8]);
            af[2] = __float_as_uint(q0[k * 8 + 4]);
            af[3] = __float_as_uint(q1[k * 8 + 4]);
            #pragma unroll
            for (int nt = 0; nt < 13; nt++) {
                uint32_t bf[2];
                const float* p = kb + nt * 8 * QSTR + k * 8;
                bf[0] = __float_as_uint(p[0]);
                bf[1] = __float_as_uint(p[4]);
                MMA_TF32(sacc[nt], af, bf);
            }
        }
    }
    __syncthreads();   // all warps done reading Q/K -> safe to overlay Ws

    {
        const int wm = wid >> 1, wn = wid & 1;
        #pragma unroll
        for (int nt = 0; nt < 13; nt++) {
            int r = wm * 16 + g;
            int n = wn * 104 + nt * 8 + 2 * tg;
            *(float2*)(Ws + r * WSTR + n) = make_float2(sacc[nt][0], sacc[nt][1]);
            *(float2*)(Ws + (r + 8) * WSTR + n) = make_float2(sacc[nt][2], sacc[nt][3]);
        }
    }
    __syncthreads();

    // ---- masked softmax (unnormalized); 4 threads per pixel
    {
        const int pix = t >> 2, sub = t & 3;
        const int gi = ti0 + (pix >> 3), gj = tj0 + (pix & 7);
        const int ro = min(max(gi - 3, 0), HH - KK) - wr0;
        const int co = min(max(gj - 3, 0), WW - KK) - wc0;
        float* wrow = Ws + pix * WSTR;

        float mx = -1e30f;
        #pragma unroll 4
        for (int i = 0; i < 52; i++) {
            int n = sub + 4 * i;
            if (n < NWIN) {
                int wr = n / WIN, wc = n - wr * WIN;
                if ((unsigned)(wr - ro) < 7u && (unsigned)(wc - co) < 7u)
                    mx = fmaxf(mx, wrow[n]);
            }
        }
        mx = fmaxf(mx, __shfl_xor_sync(0xffffffffu, mx, 1));
        mx = fmaxf(mx, __shfl_xor_sync(0xffffffffu, mx, 2));

        float lsum = 0.f;
        #pragma unroll 4
        for (int i = 0; i < 52; i++) {
            int n = sub + 4 * i;
            float w = 0.f;
            if (n < NWIN) {
                int wr = n / WIN, wc = n - wr * WIN;
                if ((unsigned)(wr - ro) < 7u && (unsigned)(wc - co) < 7u)
                    w = __expf(wrow[n] - mx);
            }
            wrow[n] = f2tf32f(w);
            lsum += w;
        }
        lsum += __shfl_xor_sync(0xffffffffu, lsum, 1);
        lsum += __shfl_xor_sync(0xffffffffu, lsum, 2);
        if (sub == 0) invs[pix] = 1.f / lsum;
    }
    __syncthreads();

    // ---- O = W * V : warp (wm 0..3, wn 0..1); 16 rows x 32 d-cols per warp.
    // B fragment read straight from K-major Vs: b = Vs[k][n] (2-way conflicts).
    {
        const int wm = wid >> 1, wn = wid & 1;
        float acc[4][4];
        #pragma unroll
        for (int nt = 0; nt < 4; nt++)
            #pragma unroll
            for (int r = 0; r < 4; r++) acc[nt][r] = 0.f;

        const float* w0 = Ws + (wm * 16 + g) * WSTR + tg;
        const float* w1 = w0 + 8 * WSTR;
        const float* vb = Vs + tg * QSTR + wn * 32 + g;   // [k=tg][n]

        #pragma unroll 2
        for (int kb = 0; kb < 26; kb++) {
            uint32_t af[4];
            af[0] = __float_as_uint(w0[kb * 8]);
            af[1] = __float_as_uint(w1[kb * 8]);
            af[2] = __float_as_uint(w0[kb * 8 + 4]);
            af[3] = __float_as_uint(w1[kb * 8 + 4]);
            const float* vk = vb + kb * 8 * QSTR;
            #pragma unroll
            for (int nt = 0; nt < 4; nt++) {
                uint32_t bf[2];
                bf[0] = __float_as_uint(vk[nt * 8]);
                bf[1] = __float_as_uint(vk[4 * QSTR + nt * 8]);
                MMA_TF32(acc[nt], af, bf);
            }
        }

        const int r = wm * 16 + g;
        const float inv0 = invs[r], inv1 = invs[r + 8];
        const int gi0 = ti0 + (r >> 3), gj0 = tj0 + (r & 7);
        const int r1 = r + 8;
        const int gi1 = ti0 + (r1 >> 3), gj1 = tj0 + (r1 & 7);
        float* o0 = out + ((size_t)b * HH * WW + (size_t)gi0 * WW + gj0) * CC + h * HD;
        float* o1 = out + ((size_t)b * HH * WW + (size_t)gi1 * WW + gj1) * CC + h * HD;
        // outputs tf32-rounded: this buffer is the A operand of the proj GEMM
        #pragma unroll
        for (int nt = 0; nt < 4; nt++) {
            int c = wn * 32 + nt * 8 + 2 * tg;
            *(float2*)(o0 + c) = make_float2(f2tf32f(acc[nt][0] * inv0), f2tf32f(acc[nt][1] * inv0));
            *(float2*)(o1 + c) = make_float2(f2tf32f(acc[nt][2] * inv1), f2tf32f(acc[nt][3] * inv1));
        }
    }
}

// ---------------------------------------------------------------------------
extern "C" void kernel_launch(void* const* d_in, const int* in_sizes, int n_in,
                              void* d_out, int out_size)
{
    (void)in_sizes; (void)n_in; (void)out_size;
    const float* x      = (const float*)d_in[0];
    const float* qkv_w  = (const float*)d_in[1];
    const float* qkv_b  = (const float*)d_in[2];
    const float* proj_w = (const float*)d_in[3];
    const float* proj_b = (const float*)d_in[4];
    float* out = (float*)d_out;

    float *qkv_s, *att_s, *x_s, *w1_s, *w2_s;
    cudaGetSymbolAddress((void**)&qkv_s, g_qkv);
    cudaGetSymbolAddress((void**)&att_s, g_att);
    cudaGetSymbolAddress((void**)&x_s,   g_x);
    cudaGetSymbolAddress((void**)&w1_s,  g_w1);
    cudaGetSymbolAddress((void**)&w2_s,  g_w2);

    cudaFuncSetAttribute(gemm_mma<96>, cudaFuncAttributeMaxDynamicSharedMemorySize, SM_GEMM_96);
    cudaFuncSetAttribute(gemm_mma<64>, cudaFuncAttributeMaxDynamicSharedMemorySize, SM_GEMM_64);
    cudaFuncSetAttribute(natt_mma, cudaFuncAttributeMaxDynamicSharedMemorySize, SM_NATT);

    // 0) pre-round GEMM inputs to tf32 (rna)
    {
        int n4x = NPIX * CC / 4;
        int n4w1 = QKV_M * CC / 4;
        int n4w2 = CC * CC / 4;
        cvt_tf32_kernel<<<(n4x + 255) / 256, 256>>>((const float4*)x, (float4*)x_s, n4x);
        cvt_tf32_kernel<<<(n4w1 + 255) / 256, 256>>>((const float4*)qkv_w, (float4*)w1_s, n4w1);
        cvt_tf32_kernel<<<(n4w2 + 255) / 256, 256>>>((const float4*)proj_w, (float4*)w2_s, n4w2);
    }
    // 1) QKV projection: BN=96 -> 576 CTAs = 1.95 waves at occ 2 (balanced)
    {
        dim3 grid(QKV_M / 96, NPIX / 128);    // (16, 36)
        gemm_mma<96><<<grid, 256, SM_GEMM_96>>>(x_s, w1_s, qkv_b, qkv_s, CC, QKV_M);
    }
    // 2) neighborhood attention (tf32 HMMA)
    {
        dim3 grid(36, NH, BATCH);
        natt_mma<<<grid, 256, SM_NATT>>>(qkv_s, att_s);
    }
    // 3) output projection: BN=64 -> 288 CTAs ~ 0.97 waves at occ 2
    {
        dim3 grid(CC / 64, NPIX / 128);       // (8, 36)
        gemm_mma<64><<<grid, 256, SM_GEMM_64>>>(att_s, w2_s, proj_b, out, CC, CC);
    }
}

// round 8
// speedup vs baseline: 1.2513x; 1.2513x over previous
#include <cuda_runtime.h>
#include <cstdint>

// Problem constants (fixed by reference setup_inputs)
#define BATCH 2
#define HH 48
#define WW 48
#define CC 512
#define NH 8
#define HD 64
#define KK 7
#define NPIX (BATCH*HH*WW)          // 4608
#define QKV_M (3*CC)                 // 1536

// Scratch (static device globals; 16B-aligned for vector access)
__device__ __align__(16) float g_qkv[(size_t)NPIX * QKV_M];   // 28.3 MB
__device__ __align__(16) float g_att[(size_t)NPIX * CC];      // 9.4 MB (tf32-rounded)
__device__ __align__(16) float g_x  [(size_t)NPIX * CC];      // 9.4 MB (tf32-rounded x)
__device__ __align__(16) float g_w1 [(size_t)QKV_M * CC];     // 3.0 MB (tf32 qkv_w)
__device__ __align__(16) float g_w2 [(size_t)CC * CC];        // 1.0 MB (tf32 proj_w)

// ---------------------------------------------------------------------------
// helpers
// ---------------------------------------------------------------------------
__device__ __forceinline__ uint32_t smem_u32(const void* p) {
    uint32_t a;
    asm("{ .reg .u64 t; cvta.to.shared.u64 t, %1; cvt.u32.u64 %0, t; }" : "=r"(a) : "l"(p));
    return a;
}
__device__ __forceinline__ uint32_t f2tf32(float x) {
    uint32_t r; asm("cvt.rna.tf32.f32 %0, %1;" : "=r"(r) : "f"(x)); return r;
}
__device__ __forceinline__ float f2tf32f(float x) {
    return __uint_as_float(f2tf32(x));
}
#define CP16(dst, src)  asm volatile("cp.async.cg.shared.global [%0], [%1], 16;" :: "r"(dst), "l"(src) : "memory")
#define CP_COMMIT()     asm volatile("cp.async.commit_group;" ::: "memory")
#define CP_WAIT(n)      asm volatile("cp.async.wait_group %0;" :: "n"(n) : "memory")

#define MMA_TF32(c, a, b) \
    asm volatile("mma.sync.aligned.m16n8k8.row.col.f32.tf32.tf32.f32 " \
        "{%0,%1,%2,%3}, {%4,%5,%6,%7}, {%8,%9}, {%0,%1,%2,%3};" \
        : "+f"((c)[0]), "+f"((c)[1]), "+f"((c)[2]), "+f"((c)[3]) \
        : "r"((a)[0]), "r"((a)[1]), "r"((a)[2]), "r"((a)[3]), "r"((b)[0]), "r"((b)[1]))

// ---------------------------------------------------------------------------
// elementwise tf32 rounding (pre-conversion of GEMM inputs)
// ---------------------------------------------------------------------------
__global__ __launch_bounds__(256) void cvt_tf32_kernel(
    const float4* __restrict__ in, float4* __restrict__ out, int n4)
{
    int i = blockIdx.x * 256 + threadIdx.x;
    if (i < n4) {
        float4 f = in[i];
        float4 o = { f2tf32f(f.x), f2tf32f(f.y), f2tf32f(f.z), f2tf32f(f.w) };
        out[i] = o;
    }
}

// ---------------------------------------------------------------------------
// tf32 warp-MMA GEMM (R6 config, BN=128 — best measured):
// C[M][Ncols] = A[M,K] * B[Ncols,K]^T + bias[Ncols]
// A, B must already be tf32-rounded. Stride 36 -> conflict-free fragments.
// ---------------------------------------------------------------------------
#define ASTR 36
#define STG_BYTES (128*ASTR*4)
#define SM_GEMM (4*STG_BYTES)        // 73728 B

__global__ __launch_bounds__(256, 2) void gemm_mma(
    const float* __restrict__ A, const float* __restrict__ B,
    const float* __restrict__ bias, float* __restrict__ C,
    int K, int Ncols)
{
    extern __shared__ float sm[];
    const uint32_t sb = smem_u32(sm);

    const int t = threadIdx.x;
    const int lane = t & 31, wid = t >> 5;
    const int g = lane >> 2, tg = lane & 3;
    const int wm = wid >> 2, wn = wid & 3;
    const int m0 = blockIdx.y * 128, n0 = blockIdx.x * 128;

    const int ldr = t >> 3;
    const int ldc = t & 7;

    float acc[4][4][4];
    #pragma unroll
    for (int i = 0; i < 4; i++)
        #pragma unroll
        for (int j = 0; j < 4; j++)
            #pragma unroll
            for (int r = 0; r < 4; r++) acc[i][j][r] = 0.f;

    const int nch = K >> 5;

    auto issue = [&](int ch, int buf) {
        const float* Ac = A + (size_t)m0 * K + ch * 32;
        const float* Bc = B + (size_t)n0 * K + ch * 32;
        uint32_t dA = sb + buf * STG_BYTES;
        uint32_t dB = sb + 2 * STG_BYTES + buf * STG_BYTES;
        #pragma unroll
        for (int i = 0; i < 4; i++) {
            int row = ldr + i * 32;
            CP16(dA + row * 144 + ldc * 16, Ac + (size_t)row * K + ldc * 4);
        }
        #pragma unroll
        for (int i = 0; i < 4; i++) {
            int row = ldr + i * 32;
            CP16(dB + row * 144 + ldc * 16, Bc + (size_t)row * K + ldc * 4);
        }
        CP_COMMIT();
    };

    issue(0, 0);

    for (int ch = 0; ch < nch; ch++) {
        const int buf = ch & 1;
        if (ch + 1 < nch) { issue(ch + 1, buf ^ 1); CP_WAIT(1); }
        else              { CP_WAIT(0); }
        __syncthreads();

        const float* Ab = sm + buf * (128 * ASTR);
        const float* Bb = sm + 2 * (128 * ASTR) + buf * (128 * ASTR);

        #pragma unroll
        for (int kk = 0; kk < 4; kk++) {
            uint32_t af[4][4], bf[4][2];
            #pragma unroll
            for (int mt = 0; mt < 4; mt++) {
                const float* p = Ab + (wm * 64 + mt * 16 + g) * ASTR + kk * 8 + tg;
                af[mt][0] = __float_as_uint(p[0]);
                af[mt][1] = __float_as_uint(p[8 * ASTR]);
                af[mt][2] = __float_as_uint(p[4]);
                af[mt][3] = __float_as_uint(p[8 * ASTR + 4]);
            }
            #pragma unroll
            for (int nt = 0; nt < 4; nt++) {
                const float* p = Bb + (wn * 32 + nt * 8 + g) * ASTR + kk * 8 + tg;
                bf[nt][0] = __float_as_uint(p[0]);
                bf[nt][1] = __float_as_uint(p[4]);
            }
            #pragma unroll
            for (int mt = 0; mt < 4; mt++)
                #pragma unroll
                for (int nt = 0; nt < 4; nt++)
                    MMA_TF32(acc[mt][nt], af[mt], bf[nt]);
        }
        __syncthreads();
    }

    float bb[4][2];
    #pragma unroll
    for (int nt = 0; nt < 4; nt++) {
        int c = n0 + wn * 32 + nt * 8 + 2 * tg;
        bb[nt][0] = __ldg(bias + c);
        bb[nt][1] = __ldg(bias + c + 1);
    }
    #pragma unroll
    for (int mt = 0; mt < 4; mt++) {
        int r = m0 + wm * 64 + mt * 16 + g;
        #pragma unroll
        for (int nt = 0; nt < 4; nt++) {
            int c = n0 + wn * 32 + nt * 8 + 2 * tg;
            float2 v0 = { acc[mt][nt][0] + bb[nt][0], acc[mt][nt][1] + bb[nt][1] };
            float2 v1 = { acc[mt][nt][2] + bb[nt][0], acc[mt][nt][3] + bb[nt][1] };
            *(float2*)(C + (size_t)r * Ncols + c) = v0;
            *(float2*)(C + (size_t)(r + 8) * Ncols + c) = v1;
        }
    }
}

// ---------------------------------------------------------------------------
// Tensor-core neighborhood attention (R4 structure + staging/softmax fixes).
// Block = (head, 8x8 pixel tile). 256 threads = 8 warps.
//   S[64,208] = Q[64,64] * Kw[208,64]^T  -> Ws (separate region, direct write)
//   masked softmax (unnormalized, divisions removed)
//   O[64,64]  = W[64,208] * Vt^T          (Vt = [d][pix], conflict-free reads)
// Staging: fully coalesced LDG; V scattered into Vt by scalar STS.
// ---------------------------------------------------------------------------
#define WIN 14
#define NWIN 196
#define NPAD 208
#define QSTR 68
#define WSTR 212

#define OFF_Q  0
#define OFF_K  (OFF_Q + 64*QSTR)            // 4352
#define OFF_V  (OFF_K + NPAD*QSTR)          // 18496   Vt[64][212]
#define OFF_W  (OFF_V + 64*WSTR)            // 32064   Ws[64][212]
#define OFF_I  (OFF_W + 64*WSTR)            // 45632
#define SM_NATT ((OFF_I + 64) * 4)          // 182784 B

__global__ __launch_bounds__(256) void natt_mma(
    const float* __restrict__ qkv, float* __restrict__ out)
{
    extern __shared__ float sm[];
    float* Qs = sm + OFF_Q;
    float* Ks = sm + OFF_K;
    float* Vt = sm + OFF_V;
    float* Ws = sm + OFF_W;
    float* invs = sm + OFF_I;

    const int tile = blockIdx.x;
    const int h = blockIdx.y;
    const int b = blockIdx.z;
    const int ti0 = (tile / 6) * 8;
    const int tj0 = (tile % 6) * 8;
    const int wr0 = min(max(ti0 - 3, 0), HH - WIN);
    const int wc0 = min(max(tj0 - 3, 0), WW - WIN);

    const int t = threadIdx.x;
    const int lane = t & 31, wid = t >> 5;
    const int g = lane >> 2, tg = lane & 3;
    const float* base = qkv + (size_t)b * HH * WW * QKV_M;

    // ---- stage Q (scaled + tf32), coalesced
    #pragma unroll
    for (int v = t; v < 64 * 16; v += 256) {
        int pix = v >> 4, dc = v & 15;
        int gi = ti0 + (pix >> 3), gj = tj0 + (pix & 7);
        float4 f = *(const float4*)(base + ((size_t)gi * WW + gj) * QKV_M + h * HD + dc * 4);
        uint4 u = { f2tf32(f.x * 0.125f), f2tf32(f.y * 0.125f),
                    f2tf32(f.z * 0.125f), f2tf32(f.w * 0.125f) };
        *(uint4*)(Qs + pix * QSTR + dc * 4) = u;
    }
    // ---- stage K [wpix][68] (vector STS) + V scattered into Vt[d][212], coalesced LDG
    for (int v = t; v < NWIN * 16; v += 256) {
        int wpix = v >> 4, dc = v & 15;
        int wr = wr0 + wpix / WIN, wc = wc0 + wpix % WIN;
        const float* p = base + ((size_t)wr * WW + wc) * QKV_M + CC + h * HD + dc * 4;
        float4 kf = *(const float4*)p;
        float4 vf = *(const float4*)(p + CC);
        uint4 ku = { f2tf32(kf.x), f2tf32(kf.y), f2tf32(kf.z), f2tf32(kf.w) };
        *(uint4*)(Ks + wpix * QSTR + dc * 4) = ku;
        int d0 = dc * 4;
        Vt[(d0 + 0) * WSTR + wpix] = f2tf32f(vf.x);
        Vt[(d0 + 1) * WSTR + wpix] = f2tf32f(vf.y);
        Vt[(d0 + 2) * WSTR + wpix] = f2tf32f(vf.z);
        Vt[(d0 + 3) * WSTR + wpix] = f2tf32f(vf.w);
    }
    // ---- zero Vt pad columns 196..211 (0-weight x garbage = NaN otherwise)
    #pragma unroll
    for (int v = t; v < 64 * 16; v += 256) {
        Vt[(v >> 4) * WSTR + NWIN + (v & 15)] = 0.f;
    }
    __syncthreads();

    // ---- QK^T: warp (wm 0..3, wn 0..1); 16 rows x 104 cols per warp
    {
        const int wm = wid >> 1, wn = wid & 1;
        float acc[13][4];
        #pragma unroll
        for (int nt = 0; nt < 13; nt++)
            #pragma unroll
            for (int r = 0; r < 4; r++) acc[nt][r] = 0.f;

        const float* q0 = Qs + (wm * 16 + g) * QSTR + tg;
        const float* q1 = q0 + 8 * QSTR;
        const float* kb = Ks + (wn * 104 + g) * QSTR + tg;

        #pragma unroll
        for (int k = 0; k < 8; k++) {
            uint32_t af[4];
            af[0] = __float_as_uint(q0[k * 8]);
            af[1] = __float_as_uint(q1[k * 8]);
            af[2] = __float_as_uint(q0[k * 8 + 4]);
            af[3] = __float_as_uint(q1[k * 8 + 4]);
            #pragma unroll
            for (int nt = 0; nt < 13; nt++) {
                uint32_t bf[2];
                const float* p = kb + nt * 8 * QSTR + k * 8;
                bf[0] = __float_as_uint(p[0]);
                bf[1] = __float_as_uint(p[4]);
                MMA_TF32(acc[nt], af, bf);
            }
        }
        // write scores straight from accumulators (Ws is a separate region)
        #pragma unroll
        for (int nt = 0; nt < 13; nt++) {
            int r = wm * 16 + g;
            int n = wn * 104 + nt * 8 + 2 * tg;
            *(float2*)(Ws + r * WSTR + n) = make_float2(acc[nt][0], acc[nt][1]);
            *(float2*)(Ws + (r + 8) * WSTR + n) = make_float2(acc[nt][2], acc[nt][3]);
        }
    }
    __syncthreads();

    // ---- masked softmax (unnormalized); 4 threads/pixel; no divisions
    {
        const int pix = t >> 2, sub = t & 3;
        const int gi = ti0 + (pix >> 3), gj = tj0 + (pix & 7);
        const int ro = min(max(gi - 3, 0), HH - KK) - wr0;
        const int co = min(max(gj - 3, 0), WW - KK) - wc0;
        float* wrow = Ws + pix * WSTR;

        // pass 1: max over valid taps (n = sub + 4i, i < 49; wr/wc incremental)
        float mx = -1e30f;
        {
            int wr = 0, wc = sub;
            #pragma unroll 7
            for (int i = 0; i < 49; i++) {
                if ((unsigned)(wr - ro) < 7u && (unsigned)(wc - co) < 7u)
                    mx = fmaxf(mx, wrow[sub + 4 * i]);
                wc += 4; if (wc >= WIN) { wc -= WIN; wr += 1; }
            }
        }
        mx = fmaxf(mx, __shfl_xor_sync(0xffffffffu, mx, 1));
        mx = fmaxf(mx, __shfl_xor_sync(0xffffffffu, mx, 2));

        // pass 2: exp + zero invalid
        float lsum = 0.f;
        {
            int wr = 0, wc = sub;
            #pragma unroll 7
            for (int i = 0; i < 49; i++) {
                int n = sub + 4 * i;
                float w = 0.f;
                if ((unsigned)(wr - ro) < 7u && (unsigned)(wc - co) < 7u)
                    w = __expf(wrow[n] - mx);
                wrow[n] = f2tf32f(w);
                lsum += w;
                wc += 4; if (wc >= WIN) { wc -= WIN; wr += 1; }
            }
        }
        lsum += __shfl_xor_sync(0xffffffffu, lsum, 1);
        lsum += __shfl_xor_sync(0xffffffffu, lsum, 2);
        if (sub == 0) invs[pix] = 1.f / lsum;
    }
    // zero Ws pad columns 196..207 (QK wrote garbage there from pad K rows)
    #pragma unroll
    for (int v = t; v < 64 * 12; v += 256) {
        int pix = v / 12, c = NWIN + (v - pix * 12);
        Ws[pix * WSTR + c] = 0.f;
    }
    __syncthreads();

    // ---- O = W * V : warp (wm 0..3, wn 0..1); 16 rows x 32 d-cols per warp
    {
        const int wm = wid >> 1, wn = wid & 1;
        float acc[4][4];
        #pragma unroll
        for (int nt = 0; nt < 4; nt++)
            #pragma unroll
            for (int r = 0; r < 4; r++) acc[nt][r] = 0.f;

        const float* w0 = Ws + (wm * 16 + g) * WSTR + tg;
        const float* w1 = w0 + 8 * WSTR;
        const float* vb = Vt + (wn * 32 + g) * WSTR + tg;

        #pragma unroll 2
        for (int kb = 0; kb < 26; kb++) {
            uint32_t af[4];
            af[0] = __float_as_uint(w0[kb * 8]);
            af[1] = __float_as_uint(w1[kb * 8]);
            af[2] = __float_as_uint(w0[kb * 8 + 4]);
            af[3] = __float_as_uint(w1[kb * 8 + 4]);
            #pragma unroll
            for (int nt = 0; nt < 4; nt++) {
                uint32_t bf[2];
                const float* p = vb + nt * 8 * WSTR + kb * 8;
                bf[0] = __float_as_uint(p[0]);
                bf[1] = __float_as_uint(p[4]);
                MMA_TF32(acc[nt], af, bf);
            }
        }

        const int r = wm * 16 + g;
        const float inv0 = invs[r], inv1 = invs[r + 8];
        const int gi0 = ti0 + (r >> 3), gj0 = tj0 + (r & 7);
        const int r1 = r + 8;
        const int gi1 = ti0 + (r1 >> 3), gj1 = tj0 + (r1 & 7);
        float* o0 = out + ((size_t)b * HH * WW + (size_t)gi0 * WW + gj0) * CC + h * HD;
        float* o1 = out + ((size_t)b * HH * WW + (size_t)gi1 * WW + gj1) * CC + h * HD;
        // outputs tf32-rounded: this buffer is the A operand of the proj GEMM
        #pragma unroll
        for (int nt = 0; nt < 4; nt++) {
            int c = wn * 32 + nt * 8 + 2 * tg;
            *(float2*)(o0 + c) = make_float2(f2tf32f(acc[nt][0] * inv0), f2tf32f(acc[nt][1] * inv0));
            *(float2*)(o1 + c) = make_float2(f2tf32f(acc[nt][2] * inv1), f2tf32f(acc[nt][3] * inv1));
        }
    }
}

// ---------------------------------------------------------------------------
extern "C" void kernel_launch(void* const* d_in, const int* in_sizes, int n_in,
                              void* d_out, int out_size)
{
    (void)in_sizes; (void)n_in; (void)out_size;
    const float* x      = (const float*)d_in[0];
    const float* qkv_w  = (const float*)d_in[1];
    const float* qkv_b  = (const float*)d_in[2];
    const float* proj_w = (const float*)d_in[3];
    const float* proj_b = (const float*)d_in[4];
    float* out = (float*)d_out;

    float *qkv_s, *att_s, *x_s, *w1_s, *w2_s;
    cudaGetSymbolAddress((void**)&qkv_s, g_qkv);
    cudaGetSymbolAddress((void**)&att_s, g_att);
    cudaGetSymbolAddress((void**)&x_s,   g_x);
    cudaGetSymbolAddress((void**)&w1_s,  g_w1);
    cudaGetSymbolAddress((void**)&w2_s,  g_w2);

    cudaFuncSetAttribute(gemm_mma, cudaFuncAttributeMaxDynamicSharedMemorySize, SM_GEMM);
    cudaFuncSetAttribute(natt_mma, cudaFuncAttributeMaxDynamicSharedMemorySize, SM_NATT);

    // 0) pre-round GEMM inputs to tf32 (rna)
    {
        int n4x = NPIX * CC / 4;
        int n4w1 = QKV_M * CC / 4;
        int n4w2 = CC * CC / 4;
        cvt_tf32_kernel<<<(n4x + 255) / 256, 256>>>((const float4*)x, (float4*)x_s, n4x);
        cvt_tf32_kernel<<<(n4w1 + 255) / 256, 256>>>((const float4*)qkv_w, (float4*)w1_s, n4w1);
        cvt_tf32_kernel<<<(n4w2 + 255) / 256, 256>>>((const float4*)proj_w, (float4*)w2_s, n4w2);
    }
    // 1) QKV projection (tf32 HMMA, BN=128)
    {
        dim3 grid(QKV_M / 128, NPIX / 128);   // (12, 36)
        gemm_mma<<<grid, 256, SM_GEMM>>>(x_s, w1_s, qkv_b, qkv_s, CC, QKV_M);
    }
    // 2) neighborhood attention (tf32 HMMA)
    {
        dim3 grid(36, NH, BATCH);
        natt_mma<<<grid, 256, SM_NATT>>>(qkv_s, att_s);
    }
    // 3) output projection (BN=128)
    {
        dim3 grid(CC / 128, NPIX / 128);      // (4, 36)
        gemm_mma<<<grid, 256, SM_GEMM>>>(att_s, w2_s, proj_b, out, CC, CC);
    }
}

// round 9
// speedup vs baseline: 1.3173x; 1.0528x over previous
#include <cuda_runtime.h>
#include <cstdint>

// Problem constants (fixed by reference setup_inputs)
#define BATCH 2
#define HH 48
#define WW 48
#define CC 512
#define NH 8
#define HD 64
#define KK 7
#define NPIX (BATCH*HH*WW)          // 4608
#define QKV_M (3*CC)                 // 1536

// Scratch (static device globals; 16B-aligned for vector access)
__device__ __align__(16) float g_qkv[(size_t)NPIX * QKV_M];   // 28.3 MB
__device__ __align__(16) float g_att[(size_t)NPIX * CC];      // 9.4 MB (tf32-rounded)
__device__ __align__(16) float g_x  [(size_t)NPIX * CC];      // 9.4 MB (tf32-rounded x)
__device__ __align__(16) float g_w1 [(size_t)QKV_M * CC];     // 3.0 MB (tf32 qkv_w)
__device__ __align__(16) float g_w2 [(size_t)CC * CC];        // 1.0 MB (tf32 proj_w)

// ---------------------------------------------------------------------------
// helpers
// ---------------------------------------------------------------------------
__device__ __forceinline__ uint32_t smem_u32(const void* p) {
    uint32_t a;
    asm("{ .reg .u64 t; cvta.to.shared.u64 t, %1; cvt.u32.u64 %0, t; }" : "=r"(a) : "l"(p));
    return a;
}
__device__ __forceinline__ uint32_t f2tf32(float x) {
    uint32_t r; asm("cvt.rna.tf32.f32 %0, %1;" : "=r"(r) : "f"(x)); return r;
}
__device__ __forceinline__ float f2tf32f(float x) {
    return __uint_as_float(f2tf32(x));
}
#define CP16(dst, src)  asm volatile("cp.async.cg.shared.global [%0], [%1], 16;" :: "r"(dst), "l"(src) : "memory")
#define CP_COMMIT()     asm volatile("cp.async.commit_group;" ::: "memory")
#define CP_WAIT(n)      asm volatile("cp.async.wait_group %0;" :: "n"(n) : "memory")

#define MMA_TF32(c, a, b) \
    asm volatile("mma.sync.aligned.m16n8k8.row.col.f32.tf32.tf32.f32 " \
        "{%0,%1,%2,%3}, {%4,%5,%6,%7}, {%8,%9}, {%0,%1,%2,%3};" \
        : "+f"((c)[0]), "+f"((c)[1]), "+f"((c)[2]), "+f"((c)[3]) \
        : "r"((a)[0]), "r"((a)[1]), "r"((a)[2]), "r"((a)[3]), "r"((b)[0]), "r"((b)[1]))

// ---------------------------------------------------------------------------
// elementwise tf32 rounding (pre-conversion of GEMM inputs)
// ---------------------------------------------------------------------------
__global__ __launch_bounds__(256) void cvt_tf32_kernel(
    const float4* __restrict__ in, float4* __restrict__ out, int n4)
{
    int i = blockIdx.x * 256 + threadIdx.x;
    if (i < n4) {
        float4 f = in[i];
        float4 o = { f2tf32f(f.x), f2tf32f(f.y), f2tf32f(f.z), f2tf32f(f.w) };
        out[i] = o;
    }
}

// ---------------------------------------------------------------------------
// tf32 warp-MMA GEMM (unchanged — best measured config):
// C[M][Ncols] = A[M,K] * B[Ncols,K]^T + bias[Ncols]
// A, B must already be tf32-rounded. Stride 36 -> conflict-free fragments.
// ---------------------------------------------------------------------------
#define ASTR 36
#define STG_BYTES (128*ASTR*4)
#define SM_GEMM (4*STG_BYTES)        // 73728 B

__global__ __launch_bounds__(256, 2) void gemm_mma(
    const float* __restrict__ A, const float* __restrict__ B,
    const float* __restrict__ bias, float* __restrict__ C,
    int K, int Ncols)
{
    extern __shared__ float sm[];
    const uint32_t sb = smem_u32(sm);

    const int t = threadIdx.x;
    const int lane = t & 31, wid = t >> 5;
    const int g = lane >> 2, tg = lane & 3;
    const int wm = wid >> 2, wn = wid & 3;
    const int m0 = blockIdx.y * 128, n0 = blockIdx.x * 128;

    const int ldr = t >> 3;
    const int ldc = t & 7;

    float acc[4][4][4];
    #pragma unroll
    for (int i = 0; i < 4; i++)
        #pragma unroll
        for (int j = 0; j < 4; j++)
            #pragma unroll
            for (int r = 0; r < 4; r++) acc[i][j][r] = 0.f;

    const int nch = K >> 5;

    auto issue = [&](int ch, int buf) {
        const float* Ac = A + (size_t)m0 * K + ch * 32;
        const float* Bc = B + (size_t)n0 * K + ch * 32;
        uint32_t dA = sb + buf * STG_BYTES;
        uint32_t dB = sb + 2 * STG_BYTES + buf * STG_BYTES;
        #pragma unroll
        for (int i = 0; i < 4; i++) {
            int row = ldr + i * 32;
            CP16(dA + row * 144 + ldc * 16, Ac + (size_t)row * K + ldc * 4);
        }
        #pragma unroll
        for (int i = 0; i < 4; i++) {
            int row = ldr + i * 32;
            CP16(dB + row * 144 + ldc * 16, Bc + (size_t)row * K + ldc * 4);
        }
        CP_COMMIT();
    };

    issue(0, 0);

    for (int ch = 0; ch < nch; ch++) {
        const int buf = ch & 1;
        if (ch + 1 < nch) { issue(ch + 1, buf ^ 1); CP_WAIT(1); }
        else              { CP_WAIT(0); }
        __syncthreads();

        const float* Ab = sm + buf * (128 * ASTR);
        const float* Bb = sm + 2 * (128 * ASTR) + buf * (128 * ASTR);

        #pragma unroll
        for (int kk = 0; kk < 4; kk++) {
            uint32_t af[4][4], bf[4][2];
            #pragma unroll
            for (int mt = 0; mt < 4; mt++) {
                const float* p = Ab + (wm * 64 + mt * 16 + g) * ASTR + kk * 8 + tg;
                af[mt][0] = __float_as_uint(p[0]);
                af[mt][1] = __float_as_uint(p[8 * ASTR]);
                af[mt][2] = __float_as_uint(p[4]);
                af[mt][3] = __float_as_uint(p[8 * ASTR + 4]);
            }
            #pragma unroll
            for (int nt = 0; nt < 4; nt++) {
                const float* p = Bb + (wn * 32 + nt * 8 + g) * ASTR + kk * 8 + tg;
                bf[nt][0] = __float_as_uint(p[0]);
                bf[nt][1] = __float_as_uint(p[4]);
            }
            #pragma unroll
            for (int mt = 0; mt < 4; mt++)
                #pragma unroll
                for (int nt = 0; nt < 4; nt++)
                    MMA_TF32(acc[mt][nt], af[mt], bf[nt]);
        }
        __syncthreads();
    }

    float bb[4][2];
    #pragma unroll
    for (int nt = 0; nt < 4; nt++) {
        int c = n0 + wn * 32 + nt * 8 + 2 * tg;
        bb[nt][0] = __ldg(bias + c);
        bb[nt][1] = __ldg(bias + c + 1);
    }
    #pragma unroll
    for (int mt = 0; mt < 4; mt++) {
        int r = m0 + wm * 64 + mt * 16 + g;
        #pragma unroll
        for (int nt = 0; nt < 4; nt++) {
            int c = n0 + wn * 32 + nt * 8 + 2 * tg;
            float2 v0 = { acc[mt][nt][0] + bb[nt][0], acc[mt][nt][1] + bb[nt][1] };
            float2 v1 = { acc[mt][nt][2] + bb[nt][0], acc[mt][nt][3] + bb[nt][1] };
            *(float2*)(C + (size_t)r * Ncols + c) = v0;
            *(float2*)(C + (size_t)(r + 8) * Ncols + c) = v1;
        }
    }
}

// ---------------------------------------------------------------------------
// Tensor-core neighborhood attention — 512 threads (16 warps) per tile.
// Block = (head, 8x8 pixel tile).
//   S[64,224] = Q[64,64] * Kw[224,64]^T   (warps 4x4: 16 rows x 56 cols)
//   masked softmax: 8 threads/pixel, unnormalized
//   O[64,64]  = W[64,224] * Vt^T          (warps 4x4: 16 rows x 16 d-cols)
// Strides: QSTR=68, WSTR=228 (both ≡4 mod 32 -> conflict-free fragments).
// ---------------------------------------------------------------------------
#define WIN 14
#define NWIN 196
#define NPAD 224
#define QSTR 68
#define WSTR 228

#define OFF_Q  0
#define OFF_K  (OFF_Q + 64*QSTR)            // 4352
#define OFF_V  (OFF_K + NPAD*QSTR)          // 19584   Vt[64][228]
#define OFF_W  (OFF_V + 64*WSTR)            // 34176   Ws[64][228]
#define OFF_I  (OFF_W + 64*WSTR)            // 48768
#define SM_NATT ((OFF_I + 64) * 4)          // 195328 B

__global__ __launch_bounds__(512) void natt_mma(
    const float* __restrict__ qkv, float* __restrict__ out)
{
    extern __shared__ float sm[];
    float* Qs = sm + OFF_Q;
    float* Ks = sm + OFF_K;
    float* Vt = sm + OFF_V;
    float* Ws = sm + OFF_W;
    float* invs = sm + OFF_I;

    const int tile = blockIdx.x;
    const int h = blockIdx.y;
    const int b = blockIdx.z;
    const int ti0 = (tile / 6) * 8;
    const int tj0 = (tile % 6) * 8;
    const int wr0 = min(max(ti0 - 3, 0), HH - WIN);
    const int wc0 = min(max(tj0 - 3, 0), WW - WIN);

    const int t = threadIdx.x;
    const int lane = t & 31, wid = t >> 5;
    const int g = lane >> 2, tg = lane & 3;
    const int wm = wid >> 2, wn = wid & 3;    // 4x4 warp grid
    const float* base = qkv + (size_t)b * HH * WW * QKV_M;

    // ---- stage Q (scaled + tf32), coalesced
    #pragma unroll
    for (int v = t; v < 64 * 16; v += 512) {
        int pix = v >> 4, dc = v & 15;
        int gi = ti0 + (pix >> 3), gj = tj0 + (pix & 7);
        float4 f = *(const float4*)(base + ((size_t)gi * WW + gj) * QKV_M + h * HD + dc * 4);
        uint4 u = { f2tf32(f.x * 0.125f), f2tf32(f.y * 0.125f),
                    f2tf32(f.z * 0.125f), f2tf32(f.w * 0.125f) };
        *(uint4*)(Qs + pix * QSTR + dc * 4) = u;
    }
    // ---- stage K [wpix][68] + V scattered into Vt[d][228], coalesced LDG
    for (int v = t; v < NWIN * 16; v += 512) {
        int wpix = v >> 4, dc = v & 15;
        int wr = wr0 + wpix / WIN, wc = wc0 + wpix % WIN;
        const float* p = base + ((size_t)wr * WW + wc) * QKV_M + CC + h * HD + dc * 4;
        float4 kf = *(const float4*)p;
        float4 vf = *(const float4*)(p + CC);
        uint4 ku = { f2tf32(kf.x), f2tf32(kf.y), f2tf32(kf.z), f2tf32(kf.w) };
        *(uint4*)(Ks + wpix * QSTR + dc * 4) = ku;
        int d0 = dc * 4;
        Vt[(d0 + 0) * WSTR + wpix] = f2tf32f(vf.x);
        Vt[(d0 + 1) * WSTR + wpix] = f2tf32f(vf.y);
        Vt[(d0 + 2) * WSTR + wpix] = f2tf32f(vf.z);
        Vt[(d0 + 3) * WSTR + wpix] = f2tf32f(vf.w);
    }
    // ---- zero K pad rows 196..223 (28 rows x 16 float4)
    for (int v = t; v < 28 * 16; v += 512) {
        int wpix = NWIN + (v >> 4), dc = v & 15;
        uint4 z = {0u, 0u, 0u, 0u};
        *(uint4*)(Ks + wpix * QSTR + dc * 4) = z;
    }
    // ---- zero Vt pad columns 196..227 (0-weight x garbage = NaN otherwise)
    #pragma unroll
    for (int v = t; v < 64 * 32; v += 512) {
        Vt[(v >> 5) * WSTR + NWIN + (v & 31)] = 0.f;
    }
    __syncthreads();

    // ---- QK^T: each warp 16 rows x 56 cols (7 n-tiles)
    {
        float acc[7][4];
        #pragma unroll
        for (int nt = 0; nt < 7; nt++)
            #pragma unroll
            for (int r = 0; r < 4; r++) acc[nt][r] = 0.f;

        const float* q0 = Qs + (wm * 16 + g) * QSTR + tg;
        const float* q1 = q0 + 8 * QSTR;
        const float* kb = Ks + (wn * 56 + g) * QSTR + tg;

        #pragma unroll
        for (int k = 0; k < 8; k++) {
            uint32_t af[4];
            af[0] = __float_as_uint(q0[k * 8]);
            af[1] = __float_as_uint(q1[k * 8]);
            af[2] = __float_as_uint(q0[k * 8 + 4]);
            af[3] = __float_as_uint(q1[k * 8 + 4]);
            #pragma unroll
            for (int nt = 0; nt < 7; nt++) {
                uint32_t bf[2];
                const float* p = kb + nt * 8 * QSTR + k * 8;
                bf[0] = __float_as_uint(p[0]);
                bf[1] = __float_as_uint(p[4]);
                MMA_TF32(acc[nt], af, bf);
            }
        }
        // write scores straight from accumulators
        #pragma unroll
        for (int nt = 0; nt < 7; nt++) {
            int r = wm * 16 + g;
            int n = wn * 56 + nt * 8 + 2 * tg;
            *(float2*)(Ws + r * WSTR + n) = make_float2(acc[nt][0], acc[nt][1]);
            *(float2*)(Ws + (r + 8) * WSTR + n) = make_float2(acc[nt][2], acc[nt][3]);
        }
    }
    __syncthreads();

    // ---- masked softmax (unnormalized); 8 threads/pixel; no divisions
    {
        const int pix = t >> 3, sub = t & 7;
        const int gi = ti0 + (pix >> 3), gj = tj0 + (pix & 7);
        const int ro = min(max(gi - 3, 0), HH - KK) - wr0;
        const int co = min(max(gj - 3, 0), WW - KK) - wc0;
        float* wrow = Ws + pix * WSTR;

        // pass 1: max over valid taps (n = sub + 8i; wr/wc incremental)
        float mx = -1e30f;
        {
            int wr = 0, wc = sub;
            #pragma unroll
            for (int i = 0; i < 25; i++) {
                int n = sub + 8 * i;
                if (n < NWIN && (unsigned)(wr - ro) < 7u && (unsigned)(wc - co) < 7u)
                    mx = fmaxf(mx, wrow[n]);
                wc += 8; if (wc >= WIN) { wc -= WIN; wr += 1; }
            }
        }
        mx = fmaxf(mx, __shfl_xor_sync(0xffffffffu, mx, 1));
        mx = fmaxf(mx, __shfl_xor_sync(0xffffffffu, mx, 2));
        mx = fmaxf(mx, __shfl_xor_sync(0xffffffffu, mx, 4));

        // pass 2: exp + zero invalid
        float lsum = 0.f;
        {
            int wr = 0, wc = sub;
            #pragma unroll
            for (int i = 0; i < 25; i++) {
                int n = sub + 8 * i;
                if (n < NWIN) {
                    float w = 0.f;
                    if ((unsigned)(wr - ro) < 7u && (unsigned)(wc - co) < 7u)
                        w = __expf(wrow[n] - mx);
                    wrow[n] = f2tf32f(w);
                    lsum += w;
                }
                wc += 8; if (wc >= WIN) { wc -= WIN; wr += 1; }
            }
        }
        lsum += __shfl_xor_sync(0xffffffffu, lsum, 1);
        lsum += __shfl_xor_sync(0xffffffffu, lsum, 2);
        lsum += __shfl_xor_sync(0xffffffffu, lsum, 4);
        if (sub == 0) invs[pix] = 1.f / lsum;
    }
    // zero Ws pad columns 196..223 (QK wrote garbage there from pad K rows)
    for (int v = t; v < 64 * 28; v += 512) {
        int pix = v / 28, c = NWIN + (v - pix * 28);
        Ws[pix * WSTR + c] = 0.f;
    }
    __syncthreads();

    // ---- O = W * V : each warp 16 rows x 16 d-cols (2 n-tiles), 28 k-tiles
    {
        float acc[2][4];
        #pragma unroll
        for (int nt = 0; nt < 2; nt++)
            #pragma unroll
            for (int r = 0; r < 4; r++) acc[nt][r] = 0.f;

        const float* w0 = Ws + (wm * 16 + g) * WSTR + tg;
        const float* w1 = w0 + 8 * WSTR;
        const float* vb = Vt + (wn * 16 + g) * WSTR + tg;

        #pragma unroll 4
        for (int kb = 0; kb < 28; kb++) {
            uint32_t af[4];
            af[0] = __float_as_uint(w0[kb * 8]);
            af[1] = __float_as_uint(w1[kb * 8]);
            af[2] = __float_as_uint(w0[kb * 8 + 4]);
            af[3] = __float_as_uint(w1[kb * 8 + 4]);
            #pragma unroll
            for (int nt = 0; nt < 2; nt++) {
                uint32_t bf[2];
                const float* p = vb + nt * 8 * WSTR + kb * 8;
                bf[0] = __float_as_uint(p[0]);
                bf[1] = __float_as_uint(p[4]);
                MMA_TF32(acc[nt], af, bf);
            }
        }

        const int r = wm * 16 + g;
        const float inv0 = invs[r], inv1 = invs[r + 8];
        const int gi0 = ti0 + (r >> 3), gj0 = tj0 + (r & 7);
        const int r1 = r + 8;
        const int gi1 = ti0 + (r1 >> 3), gj1 = tj0 + (r1 & 7);
        float* o0 = out + ((size_t)b * HH * WW + (size_t)gi0 * WW + gj0) * CC + h * HD;
        float* o1 = out + ((size_t)b * HH * WW + (size_t)gi1 * WW + gj1) * CC + h * HD;
        // outputs tf32-rounded: this buffer is the A operand of the proj GEMM
        #pragma unroll
        for (int nt = 0; nt < 2; nt++) {
            int c = wn * 16 + nt * 8 + 2 * tg;
            *(float2*)(o0 + c) = make_float2(f2tf32f(acc[nt][0] * inv0), f2tf32f(acc[nt][1] * inv0));
            *(float2*)(o1 + c) = make_float2(f2tf32f(acc[nt][2] * inv1), f2tf32f(acc[nt][3] * inv1));
        }
    }
}

// ---------------------------------------------------------------------------
extern "C" void kernel_launch(void* const* d_in, const int* in_sizes, int n_in,
                              void* d_out, int out_size)
{
    (void)in_sizes; (void)n_in; (void)out_size;
    const float* x      = (const float*)d_in[0];
    const float* qkv_w  = (const float*)d_in[1];
    const float* qkv_b  = (const float*)d_in[2];
    const float* proj_w = (const float*)d_in[3];
    const float* proj_b = (const float*)d_in[4];
    float* out = (float*)d_out;

    float *qkv_s, *att_s, *x_s, *w1_s, *w2_s;
    cudaGetSymbolAddress((void**)&qkv_s, g_qkv);
    cudaGetSymbolAddress((void**)&att_s, g_att);
    cudaGetSymbolAddress((void**)&x_s,   g_x);
    cudaGetSymbolAddress((void**)&w1_s,  g_w1);
    cudaGetSymbolAddress((void**)&w2_s,  g_w2);

    cudaFuncSetAttribute(gemm_mma, cudaFuncAttributeMaxDynamicSharedMemorySize, SM_GEMM);
    cudaFuncSetAttribute(natt_mma, cudaFuncAttributeMaxDynamicSharedMemorySize, SM_NATT);

    // 0) pre-round GEMM inputs to tf32 (rna)
    {
        int n4x = NPIX * CC / 4;
        int n4w1 = QKV_M * CC / 4;
        int n4w2 = CC * CC / 4;
        cvt_tf32_kernel<<<(n4x + 255) / 256, 256>>>((const float4*)x, (float4*)x_s, n4x);
        cvt_tf32_kernel<<<(n4w1 + 255) / 256, 256>>>((const float4*)qkv_w, (float4*)w1_s, n4w1);
        cvt_tf32_kernel<<<(n4w2 + 255) / 256, 256>>>((const float4*)proj_w, (float4*)w2_s, n4w2);
    }
    // 1) QKV projection (tf32 HMMA, BN=128)
    {
        dim3 grid(QKV_M / 128, NPIX / 128);   // (12, 36)
        gemm_mma<<<grid, 256, SM_GEMM>>>(x_s, w1_s, qkv_b, qkv_s, CC, QKV_M);
    }
    // 2) neighborhood attention (tf32 HMMA, 512 threads/tile)
    {
        dim3 grid(36, NH, BATCH);
        natt_mma<<<grid, 512, SM_NATT>>>(qkv_s, att_s);
    }
    // 3) output projection (BN=128)
    {
        dim3 grid(CC / 128, NPIX / 128);      // (4, 36)
        gemm_mma<<<grid, 256, SM_GEMM>>>(att_s, w2_s, proj_b, out, CC, CC);
    }
}